// round 13
// baseline (speedup 1.0000x reference)
#include <cuda_runtime.h>
#include <cuda_bf16.h>
#include <cstdint>

#define BATCH 1024
#define VOCAB 50000
#define DIM   300

#define BM      64
#define BN      304             // 38 n8-tiles, covers DIM=300
#define BN_ALLOC 320            // allocation/prep padding
#define KC      32              // one m16n8k32 k-step per chunk
#define SPLITS  9
#define SEG     5568            // SPLITS*SEG = 50112 >= VOCAB, mult of KC
#define K_PAD   50112
#define NCHUNK  (SEG / KC)      // 174

// fixed-point constants
#define S_W     0.051181102f            // 6.5/127 weight scale
#define INV_SW  19.538462f              // 127/6.5
#define C1      4.0300868e-4f           // S_W/127
#define C23     1.5866483e-6f           // S_W/(127*254)

// -------- static device scratch (no allocations allowed) --------
__device__ char g_bj1[(size_t)BN_ALLOC * K_PAD];   // weight digit1, [n][k]
__device__ char g_bj2[(size_t)BN_ALLOC * K_PAD];   // weight digit2, [n][k]
__device__ float g_partial[(size_t)SPLITS * BATCH * DIM];

// smem: row = 32 int8 k-bytes + 16 pad -> 48B stride.
// frag LDS.32 banks: lr*12 + lc (+4 for k+16 half) -> all 32 distinct. conflict-free.
#define A_ST 48
#define A_PLANE (64 * A_ST)          // 3072
#define B_PLANE (BN * A_ST)          // 14592
#define BUF_BYTES (2 * A_PLANE + 2 * B_PLANE)   // 35328
#define A_D1(b) ((b) * BUF_BYTES + 0)
#define A_D2(b) ((b) * BUF_BYTES + A_PLANE)
#define B_D1(b) ((b) * BUF_BYTES + 2 * A_PLANE)
#define B_D2(b) ((b) * BUF_BYTES + 2 * A_PLANE + B_PLANE)
#define SMEM_TOTAL (2 * BUF_BYTES)   // 70656

__device__ __forceinline__ uint32_t smem_u32(const void* p) {
    uint32_t a;
    asm("{ .reg .u64 t; cvta.to.shared.u64 t, %1; cvt.u32.u64 %0, t; }"
        : "=r"(a) : "l"(p));
    return a;
}
__device__ __forceinline__ void cp_async16(uint32_t dst, const void* src) {
    asm volatile("{ .reg .u64 g; cvta.to.global.u64 g, %1; "
                 "cp.async.ca.shared.global [%0], [g], 16; }"
                 :: "r"(dst), "l"(src) : "memory");
}
#define CP_COMMIT() asm volatile("cp.async.commit_group;" ::: "memory")
#define CP_WAIT0()  asm volatile("cp.async.wait_group 0;" ::: "memory")

__device__ __forceinline__ void imma16832(int* d, const uint32_t* a,
                                          uint32_t b0, uint32_t b1) {
    asm volatile("mma.sync.aligned.m16n8k32.row.col.s32.s8.s8.s32 "
                 "{%0,%1,%2,%3}, {%4,%5,%6,%7}, {%8,%9}, {%0,%1,%2,%3};"
                 : "+r"(d[0]), "+r"(d[1]), "+r"(d[2]), "+r"(d[3])
                 : "r"(a[0]), "r"(a[1]), "r"(a[2]), "r"(a[3]), "r"(b0), "r"(b1));
}

__device__ __forceinline__ uint32_t pack4(int b0, int b1, int b2, int b3) {
    return (uint32_t)(b0 & 0xFF) | ((uint32_t)(b1 & 0xFF) << 8) |
           ((uint32_t)(b2 & 0xFF) << 16) | ((uint32_t)(b3 & 0xFF) << 24);
}

// ---------------- prep: weight f32 [K][300] -> 2-digit int8 planes [320][K_PAD] --------
__global__ __launch_bounds__(256) void prep_kernel(const float* __restrict__ weight)
{
    __shared__ float t[64][65];
    const int k0 = blockIdx.x * 64;
    const int n0 = blockIdx.y * 64;
    const int tn = threadIdx.x & 63;
    const int tk = threadIdx.x >> 6;          // 0..3
#pragma unroll
    for (int i = 0; i < 16; i++) {
        const int k = k0 + tk + i * 4;
        const int n = n0 + tn;
        t[tk + i * 4][tn] = (k < VOCAB && n < DIM) ? weight[(size_t)k * DIM + n] : 0.f;
    }
    __syncthreads();
    const int nl = threadIdx.x >> 2;           // 0..63
    const int kg = (threadIdx.x & 3) * 16;     // 16 consecutive k
    uint32_t p1[4], p2[4];
#pragma unroll
    for (int q = 0; q < 4; q++) {
        int j1[4], j2[4];
#pragma unroll
        for (int b = 0; b < 4; b++) {
            const float w = t[kg + q * 4 + b][nl];
            int v1 = __float2int_rn(w * INV_SW);
            v1 = max(-127, min(127, v1));
            const float r = fmaf((float)v1, -S_W, w);
            int v2 = __float2int_rn(r * (254.0f * INV_SW));
            v2 = max(-127, min(127, v2));
            j1[b] = v1; j2[b] = v2;
        }
        p1[q] = pack4(j1[0], j1[1], j1[2], j1[3]);
        p2[q] = pack4(j2[0], j2[1], j2[2], j2[3]);
    }
    const size_t off = (size_t)(n0 + nl) * K_PAD + k0 + kg;
    *reinterpret_cast<uint4*>(g_bj1 + off) = make_uint4(p1[0], p1[1], p1[2], p1[3]);
    *reinterpret_cast<uint4*>(g_bj2 + off) = make_uint4(p2[0], p2[1], p2[2], p2[3]);
}

// ---------------- GEMM: IMMA s8 2-digit fixed point, split-K ----------------
__global__ __launch_bounds__(256, 1) void gemm_kernel(const float* __restrict__ labels)
{
    extern __shared__ char smem[];
    const uint32_t smem_base = smem_u32(smem);

    const int tid = threadIdx.x;
    const int wid = tid >> 5;
    const int lane = tid & 31;
    const int lr = lane >> 2;            // 0..7
    const int lc = lane & 3;             // 0..3
    const int m_strip = wid & 3;         // 4 m16 strips
    const int nt0 = (wid >> 2) * 19;     // n-tile base: 0 or 19

    const int row0 = blockIdx.x * BM;
    const int s = blockIdx.y;
    const int k_start = s * SEG;

    // A f32 staging indices
    const int arow = tid >> 3;           // 0..31 (rows r and r+32)
    const int af4 = tid & 7;             // float4 col 0..7

    int d1[19][4], d23[19][4];
#pragma unroll
    for (int nt = 0; nt < 19; nt++)
#pragma unroll
        for (int i = 0; i < 4; i++) { d1[nt][i] = 0; d23[nt][i] = 0; }

    auto loadA = [&](int kc0, float4* v) {
#pragma unroll
        for (int i = 0; i < 2; i++) {
            const int r = row0 + arow + i * 32;
            const int k = kc0 + af4 * 4;
            const float* src = labels + (size_t)r * VOCAB + k;
            if (k + 3 < VOCAB) {
                v[i] = *reinterpret_cast<const float4*>(src);
            } else {
                v[i].x = (k     < VOCAB) ? src[0] : 0.f;
                v[i].y = (k + 1 < VOCAB) ? src[1] : 0.f;
                v[i].z = (k + 2 < VOCAB) ? src[2] : 0.f;
                v[i].w = (k + 3 < VOCAB) ? src[3] : 0.f;
            }
        }
    };
    // convert 4 f32 -> (i1,i2) digit bytes, store one u32 per plane per row
    auto stsA = [&](int buf, const float4* v) {
#pragma unroll
        for (int i = 0; i < 2; i++) {
            const float a[4] = {v[i].x, v[i].y, v[i].z, v[i].w};
            int i1[4], i2[4];
#pragma unroll
            for (int b = 0; b < 4; b++) {
                const int q1 = __float2int_rn(a[b] * 127.0f);
                const float r1 = fmaf((float)q1, -(1.0f / 127.0f), a[b]);
                i1[b] = q1;
                i2[b] = __float2int_rn(r1 * 32258.0f);
            }
            const int off = (arow + i * 32) * A_ST + af4 * 4;
            *reinterpret_cast<uint32_t*>(smem + A_D1(buf) + off) =
                pack4(i1[0], i1[1], i1[2], i1[3]);
            *reinterpret_cast<uint32_t*>(smem + A_D2(buf) + off) =
                pack4(i2[0], i2[1], i2[2], i2[3]);
        }
    };
    auto loadB = [&](int kc0, int buf) {
#pragma unroll
        for (int i = 0; i < 3; i++) {
            const int idx = tid + 256 * i;     // need idx < 304*2 = 608
            if (idx < BN * 2) {
                const int n = idx >> 1;
                const int seg = idx & 1;
                const int doff = n * A_ST + seg * 16;
                const size_t goff = (size_t)n * K_PAD + kc0 + seg * 16;
                cp_async16(smem_base + B_D1(buf) + doff, g_bj1 + goff);
                cp_async16(smem_base + B_D2(buf) + doff, g_bj2 + goff);
            }
        }
        CP_COMMIT();
    };
    auto compute = [&](int buf) {
        const int abase = A_D1(buf) + (m_strip * 16 + lr) * A_ST + lc * 4;
        const int bbase = B_D1(buf) + (nt0 * 8 + lr) * A_ST + lc * 4;
        // A fragments: digit1 + digit2 (4 regs each: rows lr/lr+8, k halves 0/16)
        uint32_t a1[4], a2[4];
        a1[0] = *reinterpret_cast<const uint32_t*>(smem + abase);
        a1[1] = *reinterpret_cast<const uint32_t*>(smem + abase + 8 * A_ST);
        a1[2] = *reinterpret_cast<const uint32_t*>(smem + abase + 16);
        a1[3] = *reinterpret_cast<const uint32_t*>(smem + abase + 8 * A_ST + 16);
        const int ab2 = abase + A_PLANE;
        a2[0] = *reinterpret_cast<const uint32_t*>(smem + ab2);
        a2[1] = *reinterpret_cast<const uint32_t*>(smem + ab2 + 8 * A_ST);
        a2[2] = *reinterpret_cast<const uint32_t*>(smem + ab2 + 16);
        a2[3] = *reinterpret_cast<const uint32_t*>(smem + ab2 + 8 * A_ST + 16);
        // T1: d1 += a1*b1 ; T2: d23 += a1*b2 ; T3: d23 += a2*b1  (i2*j2 dropped)
#pragma unroll
        for (int nt = 0; nt < 19; nt++) {
            const int b0 = bbase + nt * 8 * A_ST;
            const uint32_t b1lo = *reinterpret_cast<const uint32_t*>(smem + b0);
            const uint32_t b1hi = *reinterpret_cast<const uint32_t*>(smem + b0 + 16);
            imma16832(d1[nt], a1, b1lo, b1hi);
            const int b2 = b0 + B_PLANE;
            const uint32_t b2lo = *reinterpret_cast<const uint32_t*>(smem + b2);
            const uint32_t b2hi = *reinterpret_cast<const uint32_t*>(smem + b2 + 16);
            imma16832(d23[nt], a1, b2lo, b2hi);
            imma16832(d23[nt], a2, b1lo, b1hi);
        }
    };

    // ---- prologue: stage chunk 0 ----
    {
        float4 v[2];
        loadB(k_start, 0);
        loadA(k_start, v);
        stsA(0, v);
        CP_WAIT0();
        __syncthreads();
    }

    // ---- main loop: issue loads early, hide LDG/cp.async under compute ----
    for (int c = 0; c < NCHUNK; c++) {
        const int buf = c & 1;
        const bool has_next = (c + 1 < NCHUNK);
        float4 v[2];
        if (has_next) {
            loadB(k_start + (c + 1) * KC, buf ^ 1);
            loadA(k_start + (c + 1) * KC, v);
        }
        compute(buf);
        if (has_next) {
            stsA(buf ^ 1, v);
            CP_WAIT0();
        }
        __syncthreads();
    }

    // ---- epilogue: dequantize, write split-K partials ----
    float* outp = g_partial + (size_t)s * BATCH * DIM;
    const int r0 = row0 + m_strip * 16 + lr;
#pragma unroll
    for (int nt = 0; nt < 19; nt++) {
        const int col = (nt0 + nt) * 8 + 2 * lc;
        if (col < DIM) {
            float f0 = (float)d1[nt][0] * C1 + (float)d23[nt][0] * C23;
            float f1 = (float)d1[nt][1] * C1 + (float)d23[nt][1] * C23;
            float f2 = (float)d1[nt][2] * C1 + (float)d23[nt][2] * C23;
            float f3 = (float)d1[nt][3] * C1 + (float)d23[nt][3] * C23;
            outp[(size_t)r0 * DIM + col] = f0;
            if (col + 1 < DIM) outp[(size_t)r0 * DIM + col + 1] = f1;
            outp[(size_t)(r0 + 8) * DIM + col] = f2;
            if (col + 1 < DIM) outp[(size_t)(r0 + 8) * DIM + col + 1] = f3;
        }
    }
}

// ---------------- reduce + L2 normalize (shfl-based) ----------------
__global__ __launch_bounds__(320) void reduce_norm_kernel(float* __restrict__ out)
{
    __shared__ float wsum[10];
    const int b = blockIdx.x;
    const int tid = threadIdx.x;

    float attr = 0.f;
    if (tid < DIM) {
#pragma unroll
        for (int s = 0; s < SPLITS; s++)
            attr += g_partial[((size_t)s * BATCH + b) * DIM + tid];
    }
    float sq = attr * attr;
#pragma unroll
    for (int off = 16; off > 0; off >>= 1)
        sq += __shfl_xor_sync(0xFFFFFFFFu, sq, off);
    if ((tid & 31) == 0) wsum[tid >> 5] = sq;
    __syncthreads();
    float total = 0.f;
#pragma unroll
    for (int w = 0; w < 10; w++) total += wsum[w];
    const float inv = 1.f / (sqrtf(total) + 1e-7f);
    if (tid < DIM) out[(size_t)b * DIM + tid] = attr * inv;
}

extern "C" void kernel_launch(void* const* d_in, const int* in_sizes, int n_in,
                              void* d_out, int out_size)
{
    const float* labels = (const float*)d_in[0];   // (1024, 50000)
    const float* weight = (const float*)d_in[1];   // (50000, 300)
    float* out = (float*)d_out;                    // (1024, 300)

    cudaFuncSetAttribute(gemm_kernel, cudaFuncAttributeMaxDynamicSharedMemorySize,
                         SMEM_TOTAL);

    prep_kernel<<<dim3(K_PAD / 64, BN_ALLOC / 64), 256>>>(weight);
    gemm_kernel<<<dim3(BATCH / BM, SPLITS), 256, SMEM_TOTAL>>>(labels);
    reduce_norm_kernel<<<BATCH, 320>>>(out);
}

// round 14
// speedup vs baseline: 1.7825x; 1.7825x over previous
#include <cuda_runtime.h>
#include <cstdint>

#define BATCH 1024
#define VOCAB 50000
#define DIM   300

#define BM      64
#define BN      304             // 38 n8-tiles, covers DIM=300
#define BN_ALLOC 320            // allocation/prep padding
#define KC      32              // 4 k-steps of m16n8k8 per chunk
#define SPLITS  9
#define SEG     5568            // SPLITS*SEG = 50112 >= VOCAB, mult of KC
#define K_PAD   50112
#define NCHUNK  (SEG / KC)      // 174

// -------- static device scratch (no allocations allowed) --------
__device__ float g_bw[(size_t)BN_ALLOC * K_PAD];   // weight tf32-rounded, [n][k] (64 MB)
__device__ float g_partial[(size_t)SPLITS * BATCH * DIM];

// smem: row = 32 f32 = 128B data + 16B pad -> 144B stride.
// frag LDS word index: row*36 + k  ->  (row*4 + k) mod 32: all 32 lanes distinct.
#define A_ST 144
#define A_PLANE (64 * A_ST)          // 9216
#define B_PLANE (BN * A_ST)          // 43776
#define BUF_BYTES (A_PLANE + B_PLANE)   // 52992
#define A_OFF(b) ((b) * BUF_BYTES)
#define B_OFF(b) ((b) * BUF_BYTES + A_PLANE)
#define SMEM_TOTAL (2 * BUF_BYTES)   // 105984

__device__ __forceinline__ uint32_t smem_u32(const void* p) {
    uint32_t a;
    asm("{ .reg .u64 t; cvta.to.shared.u64 t, %1; cvt.u32.u64 %0, t; }"
        : "=r"(a) : "l"(p));
    return a;
}
__device__ __forceinline__ void cp_async16(uint32_t dst, const void* src) {
    asm volatile("{ .reg .u64 g; cvta.to.global.u64 g, %1; "
                 "cp.async.ca.shared.global [%0], [g], 16; }"
                 :: "r"(dst), "l"(src) : "memory");
}
#define CP_COMMIT() asm volatile("cp.async.commit_group;" ::: "memory")
#define CP_WAIT0()  asm volatile("cp.async.wait_group 0;" ::: "memory")

__device__ __forceinline__ uint32_t to_tf32(float x) {
    uint32_t r;
    asm("cvt.rna.tf32.f32 %0, %1;" : "=r"(r) : "f"(x));
    return r;
}
__device__ __forceinline__ void mma_tf32(float* d, const uint32_t* a,
                                         uint32_t b0, uint32_t b1) {
    asm volatile("mma.sync.aligned.m16n8k8.row.col.f32.tf32.tf32.f32 "
                 "{%0,%1,%2,%3}, {%4,%5,%6,%7}, {%8,%9}, {%0,%1,%2,%3};"
                 : "+f"(d[0]), "+f"(d[1]), "+f"(d[2]), "+f"(d[3])
                 : "r"(a[0]), "r"(a[1]), "r"(a[2]), "r"(a[3]), "r"(b0), "r"(b1));
}

// ---------------- prep: weight f32 [K][300] -> tf32-rounded f32 [320][K_PAD] -----------
__global__ __launch_bounds__(256) void prep_kernel(const float* __restrict__ weight)
{
    __shared__ float t[64][65];
    const int k0 = blockIdx.x * 64;
    const int n0 = blockIdx.y * 64;
    const int tn = threadIdx.x & 63;
    const int tk = threadIdx.x >> 6;          // 0..3
#pragma unroll
    for (int i = 0; i < 16; i++) {
        const int k = k0 + tk + i * 4;
        const int n = n0 + tn;
        t[tk + i * 4][tn] = (k < VOCAB && n < DIM) ? weight[(size_t)k * DIM + n] : 0.f;
    }
    __syncthreads();
    const int nl = threadIdx.x >> 2;           // 0..63
    const int kg = (threadIdx.x & 3) * 16;     // 16 consecutive k
    uint32_t w[16];
#pragma unroll
    for (int j = 0; j < 16; j++) w[j] = to_tf32(t[kg + j][nl]);
    const size_t off = (size_t)(n0 + nl) * K_PAD + k0 + kg;
#pragma unroll
    for (int q = 0; q < 4; q++)
        *reinterpret_cast<uint4*>(g_bw + off + q * 4) =
            make_uint4(w[4 * q], w[4 * q + 1], w[4 * q + 2], w[4 * q + 3]);
}

// ---------------- GEMM: TF32 single-pass HMMA, split-K ----------------
__global__ __launch_bounds__(256, 1) void gemm_kernel(const float* __restrict__ labels)
{
    extern __shared__ char smem[];
    const uint32_t smem_base = smem_u32(smem);

    const int tid = threadIdx.x;
    const int wid = tid >> 5;
    const int lane = tid & 31;
    const int lr = lane >> 2;            // 0..7
    const int lc = lane & 3;             // 0..3
    const int m_strip = wid & 3;         // 4 m16 strips
    const int nt0 = (wid >> 2) * 19;     // n-tile base: 0 or 19

    const int row0 = blockIdx.x * BM;
    const int s = blockIdx.y;
    const int k_start = s * SEG;

    // A staging: 4 threads/row, each 2 float4 (8 k)
    const int arow = tid >> 2;           // 0..63
    const int af = tid & 3;              // quarter: k base = af*8

    float acc[19][4];
#pragma unroll
    for (int nt = 0; nt < 19; nt++)
#pragma unroll
        for (int i = 0; i < 4; i++) acc[nt][i] = 0.f;

    auto loadA = [&](int kc0, float4* v) {
        const float* src = labels + (size_t)(row0 + arow) * VOCAB;
#pragma unroll
        for (int j = 0; j < 2; j++) {
            const int k = kc0 + af * 8 + j * 4;
            if (k + 3 < VOCAB) {
                v[j] = *reinterpret_cast<const float4*>(src + k);
            } else {
                v[j].x = (k     < VOCAB) ? src[k]     : 0.f;
                v[j].y = (k + 1 < VOCAB) ? src[k + 1] : 0.f;
                v[j].z = (k + 2 < VOCAB) ? src[k + 2] : 0.f;
                v[j].w = (k + 3 < VOCAB) ? src[k + 3] : 0.f;
            }
        }
    };
    auto stsA = [&](int buf, const float4* v) {
#pragma unroll
        for (int j = 0; j < 2; j++) {
            uint4 p;
            p.x = to_tf32(v[j].x); p.y = to_tf32(v[j].y);
            p.z = to_tf32(v[j].z); p.w = to_tf32(v[j].w);
            const int off = arow * A_ST + af * 32 + j * 16;
            *reinterpret_cast<uint4*>(smem + A_OFF(buf) + off) = p;
        }
    };
    auto loadB = [&](int kc0, int buf) {
#pragma unroll
        for (int i = 0; i < 10; i++) {
            const int idx = tid + 256 * i;     // need idx < 304*8 = 2432
            if (idx < BN * 8) {
                const int n = idx >> 3;
                const int seg = idx & 7;
                const int doff = n * A_ST + seg * 16;
                const size_t goff = (size_t)n * K_PAD + kc0 + seg * 4;
                cp_async16(smem_base + B_OFF(buf) + doff, g_bw + goff);
            }
        }
        CP_COMMIT();
    };
    auto compute = [&](int buf) {
        const int abase = A_OFF(buf) + (m_strip * 16 + lr) * A_ST + lc * 4;
        const int bbase = B_OFF(buf) + (nt0 * 8 + lr) * A_ST + lc * 4;
#pragma unroll
        for (int kk = 0; kk < 4; kk++) {
            const int a0 = abase + kk * 32;
            uint32_t a[4];
            a[0] = *reinterpret_cast<const uint32_t*>(smem + a0);
            a[1] = *reinterpret_cast<const uint32_t*>(smem + a0 + 8 * A_ST);
            a[2] = *reinterpret_cast<const uint32_t*>(smem + a0 + 16);
            a[3] = *reinterpret_cast<const uint32_t*>(smem + a0 + 8 * A_ST + 16);
#pragma unroll
            for (int nt = 0; nt < 19; nt++) {
                const int b0 = bbase + nt * 8 * A_ST + kk * 32;
                const uint32_t bb0 = *reinterpret_cast<const uint32_t*>(smem + b0);
                const uint32_t bb1 = *reinterpret_cast<const uint32_t*>(smem + b0 + 16);
                mma_tf32(acc[nt], a, bb0, bb1);
            }
        }
    };

    // ---- prologue: stage chunk 0 ----
    {
        float4 v[2];
        loadB(k_start, 0);
        loadA(k_start, v);
        stsA(0, v);
        CP_WAIT0();
        __syncthreads();
    }

    // ---- main loop: issue loads early, hide LDG/cp.async under compute ----
    for (int c = 0; c < NCHUNK; c++) {
        const int buf = c & 1;
        const bool has_next = (c + 1 < NCHUNK);
        float4 v[2];
        if (has_next) {
            loadB(k_start + (c + 1) * KC, buf ^ 1);   // async into other buffer
            loadA(k_start + (c + 1) * KC, v);          // LDG in flight during compute
        }
        compute(buf);
        if (has_next) {
            stsA(buf ^ 1, v);                          // consume LDG after compute
            CP_WAIT0();
        }
        __syncthreads();
    }

    // ---- epilogue: write split-K partials ----
    float* outp = g_partial + (size_t)s * BATCH * DIM;
    const int r0 = row0 + m_strip * 16 + lr;
#pragma unroll
    for (int nt = 0; nt < 19; nt++) {
        const int col = (nt0 + nt) * 8 + 2 * lc;
        if (col < DIM) {
            outp[(size_t)r0 * DIM + col] = acc[nt][0];
            if (col + 1 < DIM) outp[(size_t)r0 * DIM + col + 1] = acc[nt][1];
            outp[(size_t)(r0 + 8) * DIM + col] = acc[nt][2];
            if (col + 1 < DIM) outp[(size_t)(r0 + 8) * DIM + col + 1] = acc[nt][3];
        }
    }
}

// ---------------- reduce + L2 normalize (shfl-based) ----------------
__global__ __launch_bounds__(320) void reduce_norm_kernel(float* __restrict__ out)
{
    __shared__ float wsum[10];
    const int b = blockIdx.x;
    const int tid = threadIdx.x;

    float attr = 0.f;
    if (tid < DIM) {
#pragma unroll
        for (int s = 0; s < SPLITS; s++)
            attr += g_partial[((size_t)s * BATCH + b) * DIM + tid];
    }
    float sq = attr * attr;
#pragma unroll
    for (int off = 16; off > 0; off >>= 1)
        sq += __shfl_xor_sync(0xFFFFFFFFu, sq, off);
    if ((tid & 31) == 0) wsum[tid >> 5] = sq;
    __syncthreads();
    float total = 0.f;
#pragma unroll
    for (int w = 0; w < 10; w++) total += wsum[w];
    const float inv = 1.f / (sqrtf(total) + 1e-7f);
    if (tid < DIM) out[(size_t)b * DIM + tid] = attr * inv;
}

extern "C" void kernel_launch(void* const* d_in, const int* in_sizes, int n_in,
                              void* d_out, int out_size)
{
    const float* labels = (const float*)d_in[0];   // (1024, 50000)
    const float* weight = (const float*)d_in[1];   // (50000, 300)
    float* out = (float*)d_out;                    // (1024, 300)

    cudaFuncSetAttribute(gemm_kernel, cudaFuncAttributeMaxDynamicSharedMemorySize,
                         SMEM_TOTAL);

    prep_kernel<<<dim3(K_PAD / 64, BN_ALLOC / 64), 256>>>(weight);
    gemm_kernel<<<dim3(BATCH / BM, SPLITS), 256, SMEM_TOTAL>>>(labels);
    reduce_norm_kernel<<<BATCH, 320>>>(out);
}

// round 15
// speedup vs baseline: 3.6263x; 2.0344x over previous
#include <cuda_runtime.h>
#include <cuda_fp16.h>
#include <cstdint>

#define BATCH 1024
#define VOCAB 50000
#define DIM   300

#define BM      64
#define BN      304             // 38 n8-tiles, covers DIM=300
#define BN_ALLOC 320            // allocation/prep padding
#define KC      32
#define SPLITS  9
#define SEG     5568            // SPLITS*SEG = 50112 >= VOCAB, mult of KC
#define K_PAD   50112
#define NCHUNK  (SEG / KC)      // 174

// -------- static device scratch (no allocations allowed) --------
__device__ __half g_bw[(size_t)BN_ALLOC * K_PAD];   // weight fp16, [n][k] (32 MB)
__device__ float g_partial[(size_t)SPLITS * BATCH * DIM];

// smem: row = 32 fp16 = 64B data + 16B pad -> 80B stride (R9-proven conflict-free).
#define A_ST 80
#define A_PLANE (64 * A_ST)          // 5120
#define B_PLANE (BN * A_ST)          // 24320
#define BUF_BYTES (A_PLANE + B_PLANE)   // 29440
#define A_OFF(b) ((b) * BUF_BYTES)
#define B_OFF(b) ((b) * BUF_BYTES + A_PLANE)
#define SMEM_TOTAL (2 * BUF_BYTES)   // 58880

__device__ __forceinline__ uint32_t smem_u32(const void* p) {
    uint32_t a;
    asm("{ .reg .u64 t; cvta.to.shared.u64 t, %1; cvt.u32.u64 %0, t; }"
        : "=r"(a) : "l"(p));
    return a;
}
__device__ __forceinline__ void cp_async16(uint32_t dst, const void* src) {
    asm volatile("{ .reg .u64 g; cvta.to.global.u64 g, %1; "
                 "cp.async.ca.shared.global [%0], [g], 16; }"
                 :: "r"(dst), "l"(src) : "memory");
}
#define CP_COMMIT() asm volatile("cp.async.commit_group;" ::: "memory")
#define CP_WAIT0()  asm volatile("cp.async.wait_group 0;" ::: "memory")

__device__ __forceinline__ void mma_f16(float* d, const uint32_t* a,
                                        uint32_t b0, uint32_t b1) {
    asm volatile("mma.sync.aligned.m16n8k16.row.col.f32.f16.f16.f32 "
                 "{%0,%1,%2,%3}, {%4,%5,%6,%7}, {%8,%9}, {%0,%1,%2,%3};"
                 : "+f"(d[0]), "+f"(d[1]), "+f"(d[2]), "+f"(d[3])
                 : "r"(a[0]), "r"(a[1]), "r"(a[2]), "r"(a[3]), "r"(b0), "r"(b1));
}
// pack (x,y) -> half2 (low half = x)
__device__ __forceinline__ uint32_t pack_h2(float x, float y) {
    uint32_t r;
    asm("cvt.rn.f16x2.f32 %0, %1, %2;" : "=r"(r) : "f"(y), "f"(x));
    return r;
}

// ---------------- prep: weight f32 [K][300] -> fp16 [320][K_PAD] ----------------
__global__ __launch_bounds__(256) void prep_kernel(const float* __restrict__ weight)
{
    __shared__ float t[64][65];
    const int k0 = blockIdx.x * 64;
    const int n0 = blockIdx.y * 64;
    const int tn = threadIdx.x & 63;
    const int tk = threadIdx.x >> 6;          // 0..3
#pragma unroll
    for (int i = 0; i < 16; i++) {
        const int k = k0 + tk + i * 4;
        const int n = n0 + tn;
        t[tk + i * 4][tn] = (k < VOCAB && n < DIM) ? weight[(size_t)k * DIM + n] : 0.f;
    }
    __syncthreads();
    const int nl = threadIdx.x >> 2;           // 0..63
    const int kg = (threadIdx.x & 3) * 16;     // 16 consecutive k
    uint32_t w[8];
#pragma unroll
    for (int j = 0; j < 8; j++)
        w[j] = pack_h2(t[kg + 2 * j][nl], t[kg + 2 * j + 1][nl]);
    const size_t off = (size_t)(n0 + nl) * K_PAD + k0 + kg;
    *reinterpret_cast<uint4*>(g_bw + off)     = make_uint4(w[0], w[1], w[2], w[3]);
    *reinterpret_cast<uint4*>(g_bw + off + 8) = make_uint4(w[4], w[5], w[6], w[7]);
}

// ---------------- GEMM: fp16 single-pass HMMA, split-K ----------------
__global__ __launch_bounds__(256, 1) void gemm_kernel(const float* __restrict__ labels)
{
    extern __shared__ char smem[];
    const uint32_t smem_base = smem_u32(smem);

    const int tid = threadIdx.x;
    const int wid = tid >> 5;
    const int lane = tid & 31;
    const int lr = lane >> 2;            // 0..7
    const int lc = lane & 3;             // 0..3
    const int m_strip = wid & 3;         // 4 m16 strips
    const int nt0 = (wid >> 2) * 19;     // n-tile base: 0 or 19

    const int row0 = blockIdx.x * BM;
    const int s = blockIdx.y;
    const int k_start = s * SEG;

    // A f32 staging indices
    const int arow = tid >> 3;           // 0..31 (rows r and r+32)
    const int af4 = tid & 7;             // float4 col 0..7

    float acc[19][4];
#pragma unroll
    for (int nt = 0; nt < 19; nt++)
#pragma unroll
        for (int i = 0; i < 4; i++) acc[nt][i] = 0.f;

    auto loadA = [&](int kc0, float4* v) {
#pragma unroll
        for (int i = 0; i < 2; i++) {
            const int r = row0 + arow + i * 32;
            const int k = kc0 + af4 * 4;
            const float* src = labels + (size_t)r * VOCAB + k;
            if (k + 3 < VOCAB) {
                v[i] = *reinterpret_cast<const float4*>(src);
            } else {
                v[i].x = (k     < VOCAB) ? src[0] : 0.f;
                v[i].y = (k + 1 < VOCAB) ? src[1] : 0.f;
                v[i].z = (k + 2 < VOCAB) ? src[2] : 0.f;
                v[i].w = (k + 3 < VOCAB) ? src[3] : 0.f;
            }
        }
    };
    auto stsA = [&](int buf, const float4* v) {
#pragma unroll
        for (int i = 0; i < 2; i++) {
            uint2 p;
            p.x = pack_h2(v[i].x, v[i].y);
            p.y = pack_h2(v[i].z, v[i].w);
            const int off = (arow + i * 32) * A_ST + af4 * 8;
            *reinterpret_cast<uint2*>(smem + A_OFF(buf) + off) = p;
        }
    };
    auto loadB = [&](int kc0, int buf) {
#pragma unroll
        for (int i = 0; i < 5; i++) {
            const int idx = tid + 256 * i;     // valid < 1216
            if (idx < BN * 4) {
                const int n = idx >> 2;
                const int seg = idx & 3;
                const int doff = n * A_ST + seg * 16;
                const size_t goff = (size_t)n * K_PAD + kc0 + seg * 8;
                cp_async16(smem_base + B_OFF(buf) + doff, g_bw + goff);
            }
        }
        CP_COMMIT();
    };
    auto compute = [&](int buf) {
        const int abase = A_OFF(buf) + (m_strip * 16 + lr) * A_ST + lc * 4;
        const int bbase = B_OFF(buf) + (nt0 * 8 + lr) * A_ST + lc * 4;
#pragma unroll
        for (int kk = 0; kk < 2; kk++) {
            const int a0 = abase + kk * 32;
            uint32_t a[4];
            a[0] = *reinterpret_cast<const uint32_t*>(smem + a0);
            a[1] = *reinterpret_cast<const uint32_t*>(smem + a0 + 8 * A_ST);
            a[2] = *reinterpret_cast<const uint32_t*>(smem + a0 + 16);
            a[3] = *reinterpret_cast<const uint32_t*>(smem + a0 + 8 * A_ST + 16);
#pragma unroll
            for (int nt = 0; nt < 19; nt++) {
                const int b0 = bbase + nt * 8 * A_ST + kk * 32;
                const uint32_t bb0 = *reinterpret_cast<const uint32_t*>(smem + b0);
                const uint32_t bb1 = *reinterpret_cast<const uint32_t*>(smem + b0 + 16);
                mma_f16(acc[nt], a, bb0, bb1);
            }
        }
    };

    // ---- prologue: stage chunk 0 ----
    {
        float4 v[2];
        loadB(k_start, 0);
        loadA(k_start, v);
        stsA(0, v);
        CP_WAIT0();
        __syncthreads();
    }

    // ---- main loop: issue loads early, hide LDG/cp.async under compute ----
    for (int c = 0; c < NCHUNK; c++) {
        const int buf = c & 1;
        const bool has_next = (c + 1 < NCHUNK);
        float4 v[2];
        if (has_next) {
            loadB(k_start + (c + 1) * KC, buf ^ 1);   // async into other buffer
            loadA(k_start + (c + 1) * KC, v);          // LDG in flight during compute
        }
        compute(buf);
        if (has_next) {
            stsA(buf ^ 1, v);                          // consume LDG after compute
            CP_WAIT0();
        }
        __syncthreads();
    }

    // ---- epilogue: write split-K partials ----
    float* outp = g_partial + (size_t)s * BATCH * DIM;
    const int r0 = row0 + m_strip * 16 + lr;
#pragma unroll
    for (int nt = 0; nt < 19; nt++) {
        const int col = (nt0 + nt) * 8 + 2 * lc;
        if (col < DIM) {
            outp[(size_t)r0 * DIM + col] = acc[nt][0];
            if (col + 1 < DIM) outp[(size_t)r0 * DIM + col + 1] = acc[nt][1];
            outp[(size_t)(r0 + 8) * DIM + col] = acc[nt][2];
            if (col + 1 < DIM) outp[(size_t)(r0 + 8) * DIM + col + 1] = acc[nt][3];
        }
    }
}

// ---------------- reduce + L2 normalize (shfl-based) ----------------
__global__ __launch_bounds__(320) void reduce_norm_kernel(float* __restrict__ out)
{
    __shared__ float wsum[10];
    const int b = blockIdx.x;
    const int tid = threadIdx.x;

    float attr = 0.f;
    if (tid < DIM) {
#pragma unroll
        for (int s = 0; s < SPLITS; s++)
            attr += g_partial[((size_t)s * BATCH + b) * DIM + tid];
    }
    float sq = attr * attr;
#pragma unroll
    for (int off = 16; off > 0; off >>= 1)
        sq += __shfl_xor_sync(0xFFFFFFFFu, sq, off);
    if ((tid & 31) == 0) wsum[tid >> 5] = sq;
    __syncthreads();
    float total = 0.f;
#pragma unroll
    for (int w = 0; w < 10; w++) total += wsum[w];
    const float inv = 1.f / (sqrtf(total) + 1e-7f);
    if (tid < DIM) out[(size_t)b * DIM + tid] = attr * inv;
}

extern "C" void kernel_launch(void* const* d_in, const int* in_sizes, int n_in,
                              void* d_out, int out_size)
{
    const float* labels = (const float*)d_in[0];   // (1024, 50000)
    const float* weight = (const float*)d_in[1];   // (50000, 300)
    float* out = (float*)d_out;                    // (1024, 300)

    cudaFuncSetAttribute(gemm_kernel, cudaFuncAttributeMaxDynamicSharedMemorySize,
                         SMEM_TOTAL);

    prep_kernel<<<dim3(K_PAD / 64, BN_ALLOC / 64), 256>>>(weight);
    gemm_kernel<<<dim3(BATCH / BM, SPLITS), 256, SMEM_TOTAL>>>(labels);
    reduce_norm_kernel<<<BATCH, 320>>>(out);
}

// round 17
// speedup vs baseline: 4.2992x; 1.1856x over previous
#include <cuda_runtime.h>
#include <cuda_fp16.h>
#include <cstdint>

#define BATCH 1024
#define VOCAB 50000
#define DIM   300

#define BM      64
#define BN      304             // 38 n8-tiles, covers DIM=300
#define BN_ALLOC 320            // allocation/prep padding
#define KC      32
#define SPLITS  18
#define SEG     2784            // SPLITS*SEG = 50112 >= VOCAB; 2784 = 32*87
#define K_PAD   50112
#define NCHUNK  (SEG / KC)      // 87

// -------- static device scratch (no allocations allowed) --------
__device__ __half g_bw[(size_t)BN_ALLOC * K_PAD];   // weight fp16, [n][k] (32 MB)
__device__ float g_partial[(size_t)SPLITS * BATCH * DIM];

// smem: row = 32 fp16 = 64B data + 16B pad -> 80B stride (R9-proven conflict-free).
#define A_ST 80
#define A_PLANE (64 * A_ST)          // 5120
#define B_PLANE (BN * A_ST)          // 24320
#define BUF_BYTES (A_PLANE + B_PLANE)   // 29440
#define A_OFF(b) ((b) * BUF_BYTES)
#define B_OFF(b) ((b) * BUF_BYTES + A_PLANE)
#define SMEM_TOTAL (2 * BUF_BYTES)   // 58880 (x2 CTAs = 115 KB/SM, fits)

__device__ __forceinline__ uint32_t smem_u32(const void* p) {
    uint32_t a;
    asm("{ .reg .u64 t; cvta.to.shared.u64 t, %1; cvt.u32.u64 %0, t; }"
        : "=r"(a) : "l"(p));
    return a;
}
__device__ __forceinline__ void cp_async16(uint32_t dst, const void* src) {
    asm volatile("{ .reg .u64 g; cvta.to.global.u64 g, %1; "
                 "cp.async.ca.shared.global [%0], [g], 16; }"
                 :: "r"(dst), "l"(src) : "memory");
}
#define CP_COMMIT() asm volatile("cp.async.commit_group;" ::: "memory")
#define CP_WAIT0()  asm volatile("cp.async.wait_group 0;" ::: "memory")

__device__ __forceinline__ void mma_f16(float* d, const uint32_t* a,
                                        uint32_t b0, uint32_t b1) {
    asm volatile("mma.sync.aligned.m16n8k16.row.col.f32.f16.f16.f32 "
                 "{%0,%1,%2,%3}, {%4,%5,%6,%7}, {%8,%9}, {%0,%1,%2,%3};"
                 : "+f"(d[0]), "+f"(d[1]), "+f"(d[2]), "+f"(d[3])
                 : "r"(a[0]), "r"(a[1]), "r"(a[2]), "r"(a[3]), "r"(b0), "r"(b1));
}
// pack (x,y) -> half2 (low half = x)
__device__ __forceinline__ uint32_t pack_h2(float x, float y) {
    uint32_t r;
    asm("cvt.rn.f16x2.f32 %0, %1, %2;" : "=r"(r) : "f"(y), "f"(x));
    return r;
}

// ---------------- prep: weight f32 [K][300] -> fp16 [320][K_PAD] ----------------
__global__ __launch_bounds__(256) void prep_kernel(const float* __restrict__ weight)
{
    __shared__ float t[64][65];
    const int k0 = blockIdx.x * 64;
    const int n0 = blockIdx.y * 64;
    const int tn = threadIdx.x & 63;
    const int tk = threadIdx.x >> 6;          // 0..3
#pragma unroll
    for (int i = 0; i < 16; i++) {
        const int k = k0 + tk + i * 4;
        const int n = n0 + tn;
        t[tk + i * 4][tn] = (k < VOCAB && n < DIM) ? weight[(size_t)k * DIM + n] : 0.f;
    }
    __syncthreads();
    const int nl = threadIdx.x >> 2;           // 0..63
    const int kg = (threadIdx.x & 3) * 16;     // 16 consecutive k
    uint32_t w[8];
#pragma unroll
    for (int j = 0; j < 8; j++)
        w[j] = pack_h2(t[kg + 2 * j][nl], t[kg + 2 * j + 1][nl]);
    const size_t off = (size_t)(n0 + nl) * K_PAD + k0 + kg;
    *reinterpret_cast<uint4*>(g_bw + off)     = make_uint4(w[0], w[1], w[2], w[3]);
    *reinterpret_cast<uint4*>(g_bw + off + 8) = make_uint4(w[4], w[5], w[6], w[7]);
}

// ---------------- GEMM: fp16 single-pass HMMA, split-K, 2 CTAs/SM ----------------
__global__ __launch_bounds__(256, 2) void gemm_kernel(const float* __restrict__ labels)
{
    extern __shared__ char smem[];
    const uint32_t smem_base = smem_u32(smem);

    const int tid = threadIdx.x;
    const int wid = tid >> 5;
    const int lane = tid & 31;
    const int lr = lane >> 2;            // 0..7
    const int lc = lane & 3;             // 0..3
    const int m_strip = wid & 3;         // 4 m16 strips
    const int nt0 = (wid >> 2) * 19;     // n-tile base: 0 or 19

    const int row0 = blockIdx.x * BM;
    const int s = blockIdx.y;
    const int k_start = s * SEG;

    // A f32 staging indices
    const int arow = tid >> 3;           // 0..31 (rows r and r+32)
    const int af4 = tid & 7;             // float4 col 0..7

    float acc[19][4];
#pragma unroll
    for (int nt = 0; nt < 19; nt++)
#pragma unroll
        for (int i = 0; i < 4; i++) acc[nt][i] = 0.f;

    auto loadA = [&](int kc0, float4* v) {
#pragma unroll
        for (int i = 0; i < 2; i++) {
            const int r = row0 + arow + i * 32;
            const int k = kc0 + af4 * 4;
            const float* src = labels + (size_t)r * VOCAB + k;
            if (k + 3 < VOCAB) {
                v[i] = *reinterpret_cast<const float4*>(src);
            } else {
                v[i].x = (k     < VOCAB) ? src[0] : 0.f;
                v[i].y = (k + 1 < VOCAB) ? src[1] : 0.f;
                v[i].z = (k + 2 < VOCAB) ? src[2] : 0.f;
                v[i].w = (k + 3 < VOCAB) ? src[3] : 0.f;
            }
        }
    };
    auto stsA = [&](int buf, const float4* v) {
#pragma unroll
        for (int i = 0; i < 2; i++) {
            uint2 p;
            p.x = pack_h2(v[i].x, v[i].y);
            p.y = pack_h2(v[i].z, v[i].w);
            const int off = (arow + i * 32) * A_ST + af4 * 8;
            *reinterpret_cast<uint2*>(smem + A_OFF(buf) + off) = p;
        }
    };
    auto loadB = [&](int kc0, int buf) {
#pragma unroll
        for (int i = 0; i < 5; i++) {
            const int idx = tid + 256 * i;     // valid < 1216
            if (idx < BN * 4) {
                const int n = idx >> 2;
                const int seg = idx & 3;
                const int doff = n * A_ST + seg * 16;
                const size_t goff = (size_t)n * K_PAD + kc0 + seg * 8;
                cp_async16(smem_base + B_OFF(buf) + doff, g_bw + goff);
            }
        }
        CP_COMMIT();
    };
    auto compute = [&](int buf) {
        const int abase = A_OFF(buf) + (m_strip * 16 + lr) * A_ST + lc * 4;
        const int bbase = B_OFF(buf) + (nt0 * 8 + lr) * A_ST + lc * 4;
#pragma unroll
        for (int kk = 0; kk < 2; kk++) {
            const int a0 = abase + kk * 32;
            uint32_t a[4];
            a[0] = *reinterpret_cast<const uint32_t*>(smem + a0);
            a[1] = *reinterpret_cast<const uint32_t*>(smem + a0 + 8 * A_ST);
            a[2] = *reinterpret_cast<const uint32_t*>(smem + a0 + 16);
            a[3] = *reinterpret_cast<const uint32_t*>(smem + a0 + 8 * A_ST + 16);
#pragma unroll
            for (int nt = 0; nt < 19; nt++) {
                const int b0 = bbase + nt * 8 * A_ST + kk * 32;
                const uint32_t bb0 = *reinterpret_cast<const uint32_t*>(smem + b0);
                const uint32_t bb1 = *reinterpret_cast<const uint32_t*>(smem + b0 + 16);
                mma_f16(acc[nt], a, bb0, bb1);
            }
        }
    };

    // ---- prologue: stage chunk 0 ----
    {
        float4 v[2];
        loadB(k_start, 0);
        loadA(k_start, v);
        stsA(0, v);
        CP_WAIT0();
        __syncthreads();
    }

    // ---- main loop: issue loads early, hide LDG/cp.async under compute ----
    for (int c = 0; c < NCHUNK; c++) {
        const int buf = c & 1;
        const bool has_next = (c + 1 < NCHUNK);
        float4 v[2];
        if (has_next) {
            loadB(k_start + (c + 1) * KC, buf ^ 1);   // async into other buffer
            loadA(k_start + (c + 1) * KC, v);          // LDG in flight during compute
        }
        compute(buf);
        if (has_next) {
            stsA(buf ^ 1, v);                          // consume LDG after compute
            CP_WAIT0();
        }
        __syncthreads();
    }

    // ---- epilogue: write split-K partials ----
    float* outp = g_partial + (size_t)s * BATCH * DIM;
    const int r0 = row0 + m_strip * 16 + lr;
#pragma unroll
    for (int nt = 0; nt < 19; nt++) {
        const int col = (nt0 + nt) * 8 + 2 * lc;
        if (col < DIM) {
            outp[(size_t)r0 * DIM + col] = acc[nt][0];
            if (col + 1 < DIM) outp[(size_t)r0 * DIM + col + 1] = acc[nt][1];
            outp[(size_t)(r0 + 8) * DIM + col] = acc[nt][2];
            if (col + 1 < DIM) outp[(size_t)(r0 + 8) * DIM + col + 1] = acc[nt][3];
        }
    }
}

// ---------------- reduce + L2 normalize (shfl-based) ----------------
__global__ __launch_bounds__(320) void reduce_norm_kernel(float* __restrict__ out)
{
    __shared__ float wsum[10];
    const int b = blockIdx.x;
    const int tid = threadIdx.x;

    float attr = 0.f;
    if (tid < DIM) {
#pragma unroll
        for (int s = 0; s < SPLITS; s++)
            attr += g_partial[((size_t)s * BATCH + b) * DIM + tid];
    }
    float sq = attr * attr;
#pragma unroll
    for (int off = 16; off > 0; off >>= 1)
        sq += __shfl_xor_sync(0xFFFFFFFFu, sq, off);
    if ((tid & 31) == 0) wsum[tid >> 5] = sq;
    __syncthreads();
    float total = 0.f;
#pragma unroll
    for (int w = 0; w < 10; w++) total += wsum[w];
    const float inv = 1.f / (sqrtf(total) + 1e-7f);
    if (tid < DIM) out[(size_t)b * DIM + tid] = attr * inv;
}

extern "C" void kernel_launch(void* const* d_in, const int* in_sizes, int n_in,
                              void* d_out, int out_size)
{
    const float* labels = (const float*)d_in[0];   // (1024, 50000)
    const float* weight = (const float*)d_in[1];   // (50000, 300)
    float* out = (float*)d_out;                    // (1024, 300)

    cudaFuncSetAttribute(gemm_kernel, cudaFuncAttributeMaxDynamicSharedMemorySize,
                         SMEM_TOTAL);

    prep_kernel<<<dim3(K_PAD / 64, BN_ALLOC / 64), 256>>>(weight);
    gemm_kernel<<<dim3(BATCH / BM, SPLITS), 256, SMEM_TOTAL>>>(labels);
    reduce_norm_kernel<<<BATCH, 320>>>(out);
}